// round 8
// baseline (speedup 1.0000x reference)
#include <cuda_runtime.h>
#include <cuda_bf16.h>

#define N        1024
#define ED       256
#define HD       128
#define TSP      64        // pair-tile size
#define QK       (N * 256) // per-split qk buffer stride

// ---------------- scratch (no allocation allowed) ----------------
__device__ float g_WfA[ED * 2 * HD];     // fused-weight partial, k 0..63
__device__ float g_WfB[ED * 2 * HD];     // fused-weight partial, k 64..127
__device__ float g_biasf[2 * HD];        // fused biases (q half includes b1)
__device__ float g_qk4[4 * QK];          // qk partials, split-K=4 (e-chunks of 64)

// ---------------- kernel A: ctx + fused biases, wide-parallel --------------
__global__ void __launch_bounds__(1024)
ctxbias_kernel(const float* __restrict__ emb,
               const float* __restrict__ Wc,
               const float* __restrict__ bc,
               const float* __restrict__ bq,
               const float* __restrict__ bk,
               const float* __restrict__ b1,
               const float* __restrict__ W1) {
    __shared__ float semb[ED];
    __shared__ float part1[8][HD];     // ctx partials
    __shared__ float sqk[2][HD];       // bq+ctx, bk+ctx
    __shared__ float part2[4][256];    // bias partials
    int t = threadIdx.x;
    if (t < ED) semb[t] = emb[t];
    __syncthreads();
    {   // ctx matvec: 8 partial-threads per output h, 32-deep each
        int p = t >> 7;                // 0..7
        int h = t & 127;
        int kb = p * 32;
        const float* wp = Wc + h;
        float s = 0.f;
        #pragma unroll
        for (int k = 0; k < 32; k++)
            s = fmaf(semb[kb + k], wp[(kb + k) * HD], s);
        part1[p][h] = s;
    }
    __syncthreads();
    if (t < HD) {
        float s = bc[t];
        #pragma unroll
        for (int p = 0; p < 8; p++) s += part1[p][t];
        float ctx = fmaxf(s, 0.f);
        sqk[0][t] = bq[t] + ctx;
        sqk[1][t] = bk[t] + ctx;
    }
    __syncthreads();
    {   // bias GEMV: 4 partial-threads per output c, 32-deep each
        int p = t >> 8;                // 0..3
        int c = t & 255;
        int half = c >> 7;
        int col = c & 127;
        int kb = p * 32;
        const float* w1p = W1 + (half * HD + kb) * HD + col;
        const float* v = &sqk[half][kb];
        float s = 0.f;
        #pragma unroll
        for (int k = 0; k < 32; k++)
            s = fmaf(v[k], w1p[k * HD], s);
        part2[p][c] = s;
    }
    __syncthreads();
    if (t < 256) {
        float s = (t < HD) ? b1[t] : 0.f;
        #pragma unroll
        for (int p = 0; p < 4; p++) s += part2[p][t];
        g_biasf[t] = s;
    }
}

// ---------------- kernel B: fused weights Wf = [Wq@W1top | Wk@W1bot] ------
__global__ void __launch_bounds__(128)
wfuse_kernel(const float* __restrict__ Wq,
             const float* __restrict__ Wk,
             const float* __restrict__ W1) {
    __shared__ float AsT[64 * 65];   // [k][e], scalar-store transpose, stride 65
    __shared__ float Bs[64][32];     // [k][n]
    int nb = blockIdx.x * 32;
    int e0 = blockIdx.y * 64;
    int k0 = blockIdx.z * 64;
    int half = nb >> 7;
    int ncol = nb & 127;
    const float* A = half ? Wk : Wq;
    int t = threadIdx.x, tx = t & 7, ty = t >> 3;

    #pragma unroll
    for (int l = 0; l < 8; l++) {              // A: 64(e) x 64(k), transposed
        int idx = l * 128 + t;
        int e16 = idx & 15, i = idx >> 4;
        float4 v = *(const float4*)&A[(e0 + i) * HD + k0 + 4 * e16];
        AsT[(4 * e16 + 0) * 65 + i] = v.x;
        AsT[(4 * e16 + 1) * 65 + i] = v.y;
        AsT[(4 * e16 + 2) * 65 + i] = v.z;
        AsT[(4 * e16 + 3) * 65 + i] = v.w;
    }
    #pragma unroll
    for (int l = 0; l < 4; l++) {              // B: 64x32 floats
        int idx = l * 128 + t;
        int c4 = idx & 7, row = idx >> 3;
        *(float4*)&Bs[row][4 * c4] =
            *(const float4*)&W1[(half * HD + k0 + row) * HD + ncol + 4 * c4];
    }
    __syncthreads();

    float acc[4][4] = {};
    #pragma unroll 4
    for (int k = 0; k < 64; k++) {
        float a0 = AsT[k * 65 + 4 * ty + 0];
        float a1 = AsT[k * 65 + 4 * ty + 1];
        float a2 = AsT[k * 65 + 4 * ty + 2];
        float a3 = AsT[k * 65 + 4 * ty + 3];
        float4 b = *(const float4*)&Bs[k][4 * tx];
        acc[0][0] = fmaf(a0, b.x, acc[0][0]); acc[0][1] = fmaf(a0, b.y, acc[0][1]);
        acc[0][2] = fmaf(a0, b.z, acc[0][2]); acc[0][3] = fmaf(a0, b.w, acc[0][3]);
        acc[1][0] = fmaf(a1, b.x, acc[1][0]); acc[1][1] = fmaf(a1, b.y, acc[1][1]);
        acc[1][2] = fmaf(a1, b.z, acc[1][2]); acc[1][3] = fmaf(a1, b.w, acc[1][3]);
        acc[2][0] = fmaf(a2, b.x, acc[2][0]); acc[2][1] = fmaf(a2, b.y, acc[2][1]);
        acc[2][2] = fmaf(a2, b.z, acc[2][2]); acc[2][3] = fmaf(a2, b.w, acc[2][3]);
        acc[3][0] = fmaf(a3, b.x, acc[3][0]); acc[3][1] = fmaf(a3, b.y, acc[3][1]);
        acc[3][2] = fmaf(a3, b.z, acc[3][2]); acc[3][3] = fmaf(a3, b.w, acc[3][3]);
    }
    float* outp = blockIdx.z ? g_WfB : g_WfA;
    #pragma unroll
    for (int r = 0; r < 4; r++)
        *(float4*)&outp[(e0 + 4 * ty + r) * 256 + nb + 4 * tx] =
            make_float4(acc[r][0], acc[r][1], acc[r][2], acc[r][3]);
}

// ---------------- kernel C: GEMM qk = prev @ Wf (split-K=4) ----------------
// grid (8 n, 16 m, 4 k), 128 threads, 64x32 tile, K-chunk 64.
__global__ void __launch_bounds__(128)
gemm_kernel(const float* __restrict__ prev) {
    __shared__ float AsT[64 * 65];   // [k][m] scalar-store transpose
    __shared__ float Bs[64 * 32];    // [k][n]
    int nb = blockIdx.x * 32;
    int i0 = blockIdx.y * 64;
    int k0 = blockIdx.z * 64;
    int t = threadIdx.x, tx = t & 7, ty = t >> 3;

    #pragma unroll
    for (int l = 0; l < 8; l++) {              // A: 64(m) x 64(k), transposed
        int idx = l * 128 + t;
        int e16 = idx & 15, i = idx >> 4;
        float4 v = *(const float4*)&prev[(i0 + i) * ED + k0 + 4 * e16];
        AsT[(4 * e16 + 0) * 65 + i] = v.x;
        AsT[(4 * e16 + 1) * 65 + i] = v.y;
        AsT[(4 * e16 + 2) * 65 + i] = v.z;
        AsT[(4 * e16 + 3) * 65 + i] = v.w;
    }
    #pragma unroll
    for (int l = 0; l < 4; l++) {              // B: 64x32, sum wfuse partials
        int idx = l * 128 + t;
        int c4 = idx & 7, row = idx >> 3;
        int off = (k0 + row) * 256 + nb + 4 * c4;
        float4 a = *(const float4*)&g_WfA[off];
        float4 b = *(const float4*)&g_WfB[off];
        *(float4*)&Bs[row * 32 + 4 * c4] =
            make_float4(a.x + b.x, a.y + b.y, a.z + b.z, a.w + b.w);
    }
    __syncthreads();

    float acc[4][4] = {};
    #pragma unroll 4
    for (int k = 0; k < 64; k++) {
        float a0 = AsT[k * 65 + 4 * ty + 0];
        float a1 = AsT[k * 65 + 4 * ty + 1];
        float a2 = AsT[k * 65 + 4 * ty + 2];
        float a3 = AsT[k * 65 + 4 * ty + 3];
        float4 b = *(const float4*)&Bs[k * 32 + 4 * tx];
        acc[0][0] = fmaf(a0, b.x, acc[0][0]); acc[0][1] = fmaf(a0, b.y, acc[0][1]);
        acc[0][2] = fmaf(a0, b.z, acc[0][2]); acc[0][3] = fmaf(a0, b.w, acc[0][3]);
        acc[1][0] = fmaf(a1, b.x, acc[1][0]); acc[1][1] = fmaf(a1, b.y, acc[1][1]);
        acc[1][2] = fmaf(a1, b.z, acc[1][2]); acc[1][3] = fmaf(a1, b.w, acc[1][3]);
        acc[2][0] = fmaf(a2, b.x, acc[2][0]); acc[2][1] = fmaf(a2, b.y, acc[2][1]);
        acc[2][2] = fmaf(a2, b.z, acc[2][2]); acc[2][3] = fmaf(a2, b.w, acc[2][3]);
        acc[3][0] = fmaf(a3, b.x, acc[3][0]); acc[3][1] = fmaf(a3, b.y, acc[3][1]);
        acc[3][2] = fmaf(a3, b.z, acc[3][2]); acc[3][3] = fmaf(a3, b.w, acc[3][3]);
    }
    float* outp = g_qk4 + blockIdx.z * QK;
    #pragma unroll
    for (int r = 0; r < 4; r++)
        *(float4*)&outp[(i0 + 4 * ty + r) * 256 + nb + 4 * tx] =
            make_float4(acc[r][0], acc[r][1], acc[r][2], acc[r][3]);
}

// ---------------- kernel D: pair scores, 1024 threads, 2x2/thread ----------
// relu(x)*w == (x + |x|) * (w/2) exactly; |.| packed via and.b64 (no movs).
// w2s holds W2/2.
#define PSTEP(ACC, QP, KP, WP)                                        \
    asm("{\n\t"                                                       \
        ".reg .b64 s, a;\n\t"                                         \
        "add.rn.f32x2 s, %1, %2;\n\t"                                 \
        "and.b64 a, s, 0x7FFFFFFF7FFFFFFF;\n\t"                       \
        "add.rn.f32x2 s, s, a;\n\t"                                   \
        "fma.rn.f32x2 %0, s, %3, %0;\n\t"                             \
        "}" : "+l"(ACC) : "l"(QP), "l"(KP), "l"(WP))

__global__ void __launch_bounds__(1024, 1)
pair_kernel(const float* __restrict__ W2,
            const float* __restrict__ b2,
            float* __restrict__ out) {
    extern __shared__ float sm[];
    float* qs  = sm;                   // [64][128] swizzled, bias folded
    float* ks  = sm + TSP * HD;        // [64][128] swizzled, bias folded
    float* w2s = sm + 2 * TSP * HD;    // [128] = W2 * 0.5

    // decode 1D block id -> upper-triangular tile (it <= jt), 16x16 tiles
    int rem = blockIdx.x;
    int it = 0;
    #pragma unroll
    for (int r = 0; r < 16; r++) {
        int len = 16 - r;
        if (rem < len) { it = r; break; }
        rem -= len;
    }
    int jt = it + rem;

    int t = threadIdx.x;
    int ibase = it * TSP, jbase = jt * TSP;

    // load tiles: sum 4 split-K partials + fold fused bias
    // swizzle: word(i, h4) = i*128 + 4*(h4 ^ ((i>>1)&7))
    {
        int h4 = t & 31;
        float4 bq4 = *(const float4*)&g_biasf[4 * h4];
        float4 bk4 = *(const float4*)&g_biasf[HD + 4 * h4];
        #pragma unroll
        for (int l = 0; l < 2; l++) {
            int i = (t >> 5) + 32 * l;
            int qo = (ibase + i) * 256 + 4 * h4;
            int ko = (jbase + i) * 256 + HD + 4 * h4;
            float4 qv = bq4, kv = bk4;
            #pragma unroll
            for (int z = 0; z < 4; z++) {
                float4 qa = *(const float4*)&g_qk4[z * QK + qo];
                float4 ka = *(const float4*)&g_qk4[z * QK + ko];
                qv.x += qa.x; qv.y += qa.y; qv.z += qa.z; qv.w += qa.w;
                kv.x += ka.x; kv.y += ka.y; kv.z += ka.z; kv.w += ka.w;
            }
            int sw = 4 * (h4 ^ ((i >> 1) & 7));
            *(float4*)&qs[i * HD + sw] = qv;
            *(float4*)&ks[i * HD + sw] = kv;
        }
    }
    if (t < HD) w2s[t] = 0.5f * W2[t];
    __syncthreads();

    int tx = t & 31, ty = t >> 5;      // tx: j-pairs (32), ty: i-pairs (32)
    int i0 = 2 * ty, j0 = 2 * tx;
    int swq = ty & 7, swk = tx & 7;

    unsigned long long acc00 = 0ull, acc01 = 0ull, acc10 = 0ull, acc11 = 0ull;

    #pragma unroll 4
    for (int h4 = 0; h4 < HD / 4; h4++) {
        int hq = 4 * (h4 ^ swq);
        int hk = 4 * (h4 ^ swk);
        ulonglong2 q0 = *(const ulonglong2*)&qs[(i0 + 0) * HD + hq];
        ulonglong2 q1 = *(const ulonglong2*)&qs[(i0 + 1) * HD + hq];
        ulonglong2 k0 = *(const ulonglong2*)&ks[(j0 + 0) * HD + hk];
        ulonglong2 k1 = *(const ulonglong2*)&ks[(j0 + 1) * HD + hk];
        ulonglong2 w  = *(const ulonglong2*)&w2s[4 * h4];
        PSTEP(acc00, q0.x, k0.x, w.x); PSTEP(acc00, q0.y, k0.y, w.y);
        PSTEP(acc01, q0.x, k1.x, w.x); PSTEP(acc01, q0.y, k1.y, w.y);
        PSTEP(acc10, q1.x, k0.x, w.x); PSTEP(acc10, q1.y, k0.y, w.y);
        PSTEP(acc11, q1.x, k1.x, w.x); PSTEP(acc11, q1.y, k1.y, w.y);
    }

    float bias = b2[0];
    unsigned long long accs[2][2] = {{acc00, acc01}, {acc10, acc11}};
    #pragma unroll
    for (int a = 0; a < 2; a++) {
        int i = ibase + i0 + a;
        // row-major triu offset: i*N - i*(i+1)/2 + (j - i - 1)
        int rowoff = i * N - ((i * (i + 1)) >> 1) - i - 1;
        #pragma unroll
        for (int b = 0; b < 2; b++) {
            int j = jbase + j0 + b;
            if (i < j) {
                unsigned long long v = accs[a][b];
                float lo = __int_as_float((unsigned)v);
                float hi = __int_as_float((unsigned)(v >> 32));
                out[rowoff + j] = lo + hi + bias;
            }
        }
    }
}

// ---------------- launch ----------------
extern "C" void kernel_launch(void* const* d_in, const int* in_sizes, int n_in,
                              void* d_out, int out_size) {
    const float* emb  = (const float*)d_in[0];
    const float* prev = (const float*)d_in[1];
    const float* Wq   = (const float*)d_in[2];
    const float* bq   = (const float*)d_in[3];
    const float* Wk   = (const float*)d_in[4];
    const float* bk   = (const float*)d_in[5];
    const float* Wc   = (const float*)d_in[6];
    const float* bc   = (const float*)d_in[7];
    const float* W1   = (const float*)d_in[8];
    const float* b1   = (const float*)d_in[9];
    const float* W2   = (const float*)d_in[10];
    const float* b2   = (const float*)d_in[11];
    float* out = (float*)d_out;

    int pair_smem = (2 * TSP * HD + HD) * (int)sizeof(float);        // 66048
    cudaFuncSetAttribute(pair_kernel,
                         cudaFuncAttributeMaxDynamicSharedMemorySize, pair_smem);

    ctxbias_kernel<<<1, 1024>>>(emb, Wc, bc, bq, bk, b1, W1);
    wfuse_kernel<<<dim3(8, 4, 2), 128>>>(Wq, Wk, W1);
    gemm_kernel<<<dim3(8, 16, 4), 128>>>(prev);
    pair_kernel<<<136, 1024, pair_smem>>>(W2, b2, out);
}

// round 11
// speedup vs baseline: 1.0383x; 1.0383x over previous
#include <cuda_runtime.h>
#include <cuda_bf16.h>

#define N        1024
#define ED       256
#define HD       128
#define TSP      64
#define NB       136            // blocks; all co-resident (<=148 SMs, 1/SM)
#define QK       (N * 256)      // per-split qk buffer stride
#define GSTRIDE  (64 * 65 + 64 * 32)   // 6208 floats per tile-group

// ---------------- scratch (no allocation allowed) ----------------
__device__ float g_WfA[ED * 2 * HD];     // fused-weight partial, k 0..63
__device__ float g_WfB[ED * 2 * HD];     // fused-weight partial, k 64..127
__device__ float g_biasf[2 * HD];        // fused biases (q half includes b1)
__device__ float g_qk4[4 * QK];          // qk partials, split-K=4
__device__ unsigned g_bar1;              // zero-initialized
__device__ unsigned g_bar2;

// ticket barrier: monotonic counter, epoch = ticket/NB; replay-safe, no reset.
__device__ __forceinline__ void grid_barrier(unsigned* ctr) {
    __syncthreads();
    if (threadIdx.x == 0) {
        __threadfence();
        unsigned ticket = atomicAdd(ctr, 1u);
        unsigned target = (ticket / NB + 1u) * NB;
        while ((int)(*(volatile unsigned*)ctr - target) < 0)
            __nanosleep(20);
        __threadfence();
    }
    __syncthreads();
}

// packed step: add.f32x2 -> 2x scalar max -> fma.f32x2 (R6-proven)
#define PSTEP(ACC, QP, KP, WP)                                        \
    asm("{\n\t"                                                       \
        ".reg .b64 s; .reg .f32 lo, hi;\n\t"                          \
        "add.rn.f32x2 s, %1, %2;\n\t"                                 \
        "mov.b64 {lo, hi}, s;\n\t"                                    \
        "max.f32 lo, lo, 0f00000000;\n\t"                             \
        "max.f32 hi, hi, 0f00000000;\n\t"                             \
        "mov.b64 s, {lo, hi};\n\t"                                    \
        "fma.rn.f32x2 %0, s, %3, %0;\n\t"                             \
        "}" : "+l"(ACC) : "l"(QP), "l"(KP), "l"(WP))

__global__ void __launch_bounds__(512, 1)
mono_kernel(const float* __restrict__ emb,
            const float* __restrict__ prev,
            const float* __restrict__ Wq,
            const float* __restrict__ bq,
            const float* __restrict__ Wk,
            const float* __restrict__ bk,
            const float* __restrict__ Wc,
            const float* __restrict__ bc,
            const float* __restrict__ W1,
            const float* __restrict__ b1,
            const float* __restrict__ W2,
            const float* __restrict__ b2,
            float* __restrict__ out) {
    extern __shared__ float sm[];
    int t = threadIdx.x;
    int blk = blockIdx.x;
    int g = t >> 7, t128 = t & 127;          // 128-thread tile-group
    float* gbase = sm + g * GSTRIDE;

    // ================= PHASE 1: wfuse GEMM (blocks 0-15) + ctxbias (135) ===
    if (blk < 16) {
        // Wf = [Wq@W1top | Wk@W1bot]; 64 tiles (8n x 4e x 2k), one per group
        float* AsT = gbase;            // [64k][65e]
        float* Bs  = gbase + 64 * 65;  // [64k][32n]
        int wg = blk * 4 + g;
        int nb = (wg & 7) * 32;
        int e0 = ((wg >> 3) & 3) * 64;
        int k0 = ((wg >> 5) & 1) * 64;
        int half = nb >> 7;
        int ncol = nb & 127;
        const float* A = half ? Wk : Wq;
        int tx = t128 & 7, ty = t128 >> 3;

        #pragma unroll
        for (int l = 0; l < 8; l++) {          // A: 64(e) x 64(k), transposed
            int idx = l * 128 + t128;
            int e16 = idx & 15, i = idx >> 4;
            float4 v = *(const float4*)&A[(e0 + i) * HD + k0 + 4 * e16];
            AsT[(4 * e16 + 0) * 65 + i] = v.x;
            AsT[(4 * e16 + 1) * 65 + i] = v.y;
            AsT[(4 * e16 + 2) * 65 + i] = v.z;
            AsT[(4 * e16 + 3) * 65 + i] = v.w;
        }
        #pragma unroll
        for (int l = 0; l < 4; l++) {          // B: 64x32
            int idx = l * 128 + t128;
            int c4 = idx & 7, row = idx >> 3;
            *(float4*)&Bs[row * 32 + 4 * c4] =
                *(const float4*)&W1[(half * HD + k0 + row) * HD + ncol + 4 * c4];
        }
        __syncthreads();
        float acc[4][4] = {};
        #pragma unroll 4
        for (int k = 0; k < 64; k++) {
            float a0 = AsT[k * 65 + 4 * ty + 0];
            float a1 = AsT[k * 65 + 4 * ty + 1];
            float a2 = AsT[k * 65 + 4 * ty + 2];
            float a3 = AsT[k * 65 + 4 * ty + 3];
            float4 b = *(const float4*)&Bs[k * 32 + 4 * tx];
            acc[0][0] = fmaf(a0, b.x, acc[0][0]); acc[0][1] = fmaf(a0, b.y, acc[0][1]);
            acc[0][2] = fmaf(a0, b.z, acc[0][2]); acc[0][3] = fmaf(a0, b.w, acc[0][3]);
            acc[1][0] = fmaf(a1, b.x, acc[1][0]); acc[1][1] = fmaf(a1, b.y, acc[1][1]);
            acc[1][2] = fmaf(a1, b.z, acc[1][2]); acc[1][3] = fmaf(a1, b.w, acc[1][3]);
            acc[2][0] = fmaf(a2, b.x, acc[2][0]); acc[2][1] = fmaf(a2, b.y, acc[2][1]);
            acc[2][2] = fmaf(a2, b.z, acc[2][2]); acc[2][3] = fmaf(a2, b.w, acc[2][3]);
            acc[3][0] = fmaf(a3, b.x, acc[3][0]); acc[3][1] = fmaf(a3, b.y, acc[3][1]);
            acc[3][2] = fmaf(a3, b.z, acc[3][2]); acc[3][3] = fmaf(a3, b.w, acc[3][3]);
        }
        float* outp = ((wg >> 5) & 1) ? g_WfB : g_WfA;
        #pragma unroll
        for (int r = 0; r < 4; r++)
            *(float4*)&outp[(e0 + 4 * ty + r) * 256 + nb + 4 * tx] =
                make_float4(acc[r][0], acc[r][1], acc[r][2], acc[r][3]);
    } else if (blk == NB - 1) {
        // ctx = relu(emb@Wc+bc); fused biases. 512 threads, 8-chain MLP.
        float* semb  = sm;              // 256
        float* part1 = sm + 256;        // [4][128]
        float* sqk   = sm + 256 + 512;  // [2][128]
        float* part2 = sm + 256 + 512 + 256;  // [2][256]
        if (t < 256) semb[t] = emb[t];
        __syncthreads();
        {   // ctx matvec: 4 partials per h, 64-deep as 8 chains of 8
            int p = t >> 7, h = t & 127;
            int kb = p * 64;
            float s[8] = {};
            #pragma unroll
            for (int c = 0; c < 8; c++)
                #pragma unroll
                for (int k = 0; k < 8; k++) {
                    int idx = kb + c * 8 + k;
                    s[c] = fmaf(semb[idx], Wc[idx * HD + h], s[c]);
                }
            part1[p * 128 + h] = ((s[0]+s[1])+(s[2]+s[3]))+((s[4]+s[5])+(s[6]+s[7]));
        }
        __syncthreads();
        if (t < 128) {
            float v = bc[t] + part1[t] + part1[128 + t] + part1[256 + t] + part1[384 + t];
            float ctx = fmaxf(v, 0.f);
            sqk[t] = bq[t] + ctx;
            sqk[128 + t] = bk[t] + ctx;
        }
        __syncthreads();
        {   // bias GEMV: 2 partials per output c, 64-deep as 8 chains of 8
            int p = t >> 8;            // 0..1
            int c = t & 255;
            int half = c >> 7, col = c & 127;
            int kb = p * 64;
            float s[8] = {};
            #pragma unroll
            for (int cc = 0; cc < 8; cc++)
                #pragma unroll
                for (int k = 0; k < 8; k++) {
                    int kk = kb + cc * 8 + k;
                    s[cc] = fmaf(sqk[half * 128 + kk],
                                 W1[(half * HD + kk) * HD + col], s[cc]);
                }
            part2[p * 256 + c] =
                ((s[0]+s[1])+(s[2]+s[3]))+((s[4]+s[5])+(s[6]+s[7]));
        }
        __syncthreads();
        if (t < 256)
            g_biasf[t] = ((t < HD) ? b1[t] : 0.f) + part2[t] + part2[256 + t];
    }

    grid_barrier(&g_bar1);

    // ================= PHASE 2: qk GEMM, 512 tiles (8n x 16m x 4k) =========
    if (blk < 128) {
        float* AsT = gbase;            // [64k][65m]
        float* Bs  = gbase + 64 * 65;  // [64k][32n]
        int wg = blk * 4 + g;          // 0..511
        int nb = (wg & 7) * 32;
        int i0 = ((wg >> 3) & 15) * 64;
        int z  = wg >> 7;
        int k0 = z * 64;
        int tx = t128 & 7, ty = t128 >> 3;

        #pragma unroll
        for (int l = 0; l < 8; l++) {          // A: 64(m) x 64(k), transposed
            int idx = l * 128 + t128;
            int e16 = idx & 15, i = idx >> 4;
            float4 v = *(const float4*)&prev[(i0 + i) * ED + k0 + 4 * e16];
            AsT[(4 * e16 + 0) * 65 + i] = v.x;
            AsT[(4 * e16 + 1) * 65 + i] = v.y;
            AsT[(4 * e16 + 2) * 65 + i] = v.z;
            AsT[(4 * e16 + 3) * 65 + i] = v.w;
        }
        #pragma unroll
        for (int l = 0; l < 4; l++) {          // B: 64x32, sum wfuse partials
            int idx = l * 128 + t128;
            int c4 = idx & 7, row = idx >> 3;
            int off = (k0 + row) * 256 + nb + 4 * c4;
            float4 a = *(const float4*)&g_WfA[off];
            float4 b = *(const float4*)&g_WfB[off];
            *(float4*)&Bs[row * 32 + 4 * c4] =
                make_float4(a.x + b.x, a.y + b.y, a.z + b.z, a.w + b.w);
        }
        __syncthreads();
        float acc[4][4] = {};
        #pragma unroll 4
        for (int k = 0; k < 64; k++) {
            float a0 = AsT[k * 65 + 4 * ty + 0];
            float a1 = AsT[k * 65 + 4 * ty + 1];
            float a2 = AsT[k * 65 + 4 * ty + 2];
            float a3 = AsT[k * 65 + 4 * ty + 3];
            float4 b = *(const float4*)&Bs[k * 32 + 4 * tx];
            acc[0][0] = fmaf(a0, b.x, acc[0][0]); acc[0][1] = fmaf(a0, b.y, acc[0][1]);
            acc[0][2] = fmaf(a0, b.z, acc[0][2]); acc[0][3] = fmaf(a0, b.w, acc[0][3]);
            acc[1][0] = fmaf(a1, b.x, acc[1][0]); acc[1][1] = fmaf(a1, b.y, acc[1][1]);
            acc[1][2] = fmaf(a1, b.z, acc[1][2]); acc[1][3] = fmaf(a1, b.w, acc[1][3]);
            acc[2][0] = fmaf(a2, b.x, acc[2][0]); acc[2][1] = fmaf(a2, b.y, acc[2][1]);
            acc[2][2] = fmaf(a2, b.z, acc[2][2]); acc[2][3] = fmaf(a2, b.w, acc[2][3]);
            acc[3][0] = fmaf(a3, b.x, acc[3][0]); acc[3][1] = fmaf(a3, b.y, acc[3][1]);
            acc[3][2] = fmaf(a3, b.z, acc[3][2]); acc[3][3] = fmaf(a3, b.w, acc[3][3]);
        }
        float* outp = g_qk4 + z * QK;
        #pragma unroll
        for (int r = 0; r < 4; r++)
            *(float4*)&outp[(i0 + 4 * ty + r) * 256 + nb + 4 * tx] =
                make_float4(acc[r][0], acc[r][1], acc[r][2], acc[r][3]);
    }

    grid_barrier(&g_bar2);

    // ================= PHASE 3: pair scores (R6 body) ======================
    {
        float* qs  = sm;                      // [64][128] swizzled
        float* ks  = sm + TSP * HD;           // [64][128] swizzled
        float* w2s = sm + 2 * TSP * HD;       // [128]
        float* red = sm + 2 * TSP * HD + HD;  // [64][65] scratch

        int rem = blk;
        int it = 0;
        #pragma unroll
        for (int r = 0; r < 16; r++) {
            int len = 16 - r;
            if (rem < len) { it = r; break; }
            rem -= len;
        }
        int jt = it + rem;
        int ibase = it * TSP, jbase = jt * TSP;

        {   // loader: sum 4 split-K partials + fold fused bias, swizzle rows
            int h4 = t & 31;
            float4 bq4 = *(const float4*)&g_biasf[4 * h4];
            float4 bk4 = *(const float4*)&g_biasf[HD + 4 * h4];
            #pragma unroll
            for (int l = 0; l < 4; l++) {
                int i = (t >> 5) + 16 * l;
                int qo = (ibase + i) * 256 + 4 * h4;
                int ko = (jbase + i) * 256 + HD + 4 * h4;
                float4 qv = bq4, kv = bk4;
                #pragma unroll
                for (int z = 0; z < 4; z++) {
                    float4 qa = *(const float4*)&g_qk4[z * QK + qo];
                    float4 ka = *(const float4*)&g_qk4[z * QK + ko];
                    qv.x += qa.x; qv.y += qa.y; qv.z += qa.z; qv.w += qa.w;
                    kv.x += ka.x; kv.y += ka.y; kv.z += ka.z; kv.w += ka.w;
                }
                int sw = 4 * (h4 ^ ((i >> 2) & 7));
                *(float4*)&qs[i * HD + sw] = qv;
                *(float4*)&ks[i * HD + sw] = kv;
            }
        }
        if (t < HD) w2s[t] = W2[t];
        __syncthreads();

        int hg = t >> 8;
        int tt = t & 255;
        int tx = tt & 15, ty = tt >> 4;
        int i0 = ty * 4, j0 = tx * 4;
        int swq = ty & 7, swk = tx & 7;

        unsigned long long acc[4][4];
        #pragma unroll
        for (int a = 0; a < 4; a++)
            #pragma unroll
            for (int b = 0; b < 4; b++)
                acc[a][b] = 0ull;

        int h4beg = hg * 16;
        #pragma unroll 2
        for (int hh = 0; hh < 16; hh++) {
            int h4 = h4beg + hh;
            int hq = 4 * (h4 ^ swq);
            int hk = 4 * (h4 ^ swk);
            ulonglong2 q[4], k[4];
            #pragma unroll
            for (int a = 0; a < 4; a++)
                q[a] = *(const ulonglong2*)&qs[(i0 + a) * HD + hq];
            #pragma unroll
            for (int b = 0; b < 4; b++)
                k[b] = *(const ulonglong2*)&ks[(j0 + b) * HD + hk];
            ulonglong2 w = *(const ulonglong2*)&w2s[4 * h4];
            #pragma unroll
            for (int a = 0; a < 4; a++)
                #pragma unroll
                for (int b = 0; b < 4; b++) {
                    PSTEP(acc[a][b], q[a].x, k[b].x, w.x);
                    PSTEP(acc[a][b], q[a].y, k[b].y, w.y);
                }
        }

        float s[4][4];
        #pragma unroll
        for (int a = 0; a < 4; a++)
            #pragma unroll
            for (int b = 0; b < 4; b++) {
                unsigned long long v = acc[a][b];
                s[a][b] = __int_as_float((unsigned)v) +
                          __int_as_float((unsigned)(v >> 32));
            }

        if (hg) {
            #pragma unroll
            for (int a = 0; a < 4; a++)
                #pragma unroll
                for (int b = 0; b < 4; b++)
                    red[(i0 + a) * 65 + j0 + b] = s[a][b];
        }
        __syncthreads();

        if (!hg) {
            float bias = b2[0];
            #pragma unroll
            for (int a = 0; a < 4; a++) {
                int i = ibase + i0 + a;
                int rowoff = i * N - ((i * (i + 1)) >> 1) - i - 1;
                #pragma unroll
                for (int b = 0; b < 4; b++) {
                    int j = jbase + j0 + b;
                    if (i < j)
                        out[rowoff + j] =
                            s[a][b] + red[(i0 + a) * 65 + j0 + b] + bias;
                }
            }
        }
    }
}

// ---------------- launch ----------------
extern "C" void kernel_launch(void* const* d_in, const int* in_sizes, int n_in,
                              void* d_out, int out_size) {
    const float* emb  = (const float*)d_in[0];
    const float* prev = (const float*)d_in[1];
    const float* Wq   = (const float*)d_in[2];
    const float* bq   = (const float*)d_in[3];
    const float* Wk   = (const float*)d_in[4];
    const float* bk   = (const float*)d_in[5];
    const float* Wc   = (const float*)d_in[6];
    const float* bc   = (const float*)d_in[7];
    const float* W1   = (const float*)d_in[8];
    const float* b1   = (const float*)d_in[9];
    const float* W2   = (const float*)d_in[10];
    const float* b2   = (const float*)d_in[11];
    float* out = (float*)d_out;

    // smem = max(phase1/2: 4 groups * GSTRIDE, phase3: 20672 floats)
    int smem = 4 * GSTRIDE * (int)sizeof(float);                     // 99328
    cudaFuncSetAttribute(mono_kernel,
                         cudaFuncAttributeMaxDynamicSharedMemorySize, smem);

    mono_kernel<<<NB, 512, smem>>>(emb, prev, Wq, bq, Wk, bk, Wc, bc,
                                   W1, b1, W2, b2, out);
}

// round 12
// speedup vs baseline: 1.0703x; 1.0307x over previous
#include <cuda_runtime.h>
#include <cuda_bf16.h>

#define N        1024
#define ED       256
#define HD       128
#define TSP      64
#define NB       136            // blocks; all co-resident (<=148 SMs, 1/SM)
#define QK       (N * 256)      // per-split qk buffer stride
#define GSTRIDE  (64 * 65 + 64 * 32)   // 6208 floats per tile-group

// ---------------- scratch (no allocation allowed) ----------------
__device__ float g_WfA[ED * 2 * HD];     // fused-weight partial, k 0..63
__device__ float g_WfB[ED * 2 * HD];     // fused-weight partial, k 64..127
__device__ float g_biasf[2 * HD];        // fused biases (q half includes b1)
__device__ float g_qk4[4 * QK];          // qk partials, split-K=4
__device__ unsigned g_bar1;              // zero-initialized
__device__ unsigned g_bar2;

// ticket barrier: monotonic counter, epoch = ticket/NB; replay-safe, no reset.
__device__ __forceinline__ void grid_barrier(unsigned* ctr) {
    __syncthreads();
    if (threadIdx.x == 0) {
        __threadfence();
        unsigned ticket = atomicAdd(ctr, 1u);
        unsigned target = (ticket / NB + 1u) * NB;
        while ((int)(*(volatile unsigned*)ctr - target) < 0)
            __nanosleep(20);
        __threadfence();
    }
    __syncthreads();
}

// packed step: add.f32x2 -> 2x scalar max -> fma.f32x2 (R6-proven)
#define PSTEP(ACC, QP, KP, WP)                                        \
    asm("{\n\t"                                                       \
        ".reg .b64 s; .reg .f32 lo, hi;\n\t"                          \
        "add.rn.f32x2 s, %1, %2;\n\t"                                 \
        "mov.b64 {lo, hi}, s;\n\t"                                    \
        "max.f32 lo, lo, 0f00000000;\n\t"                             \
        "max.f32 hi, hi, 0f00000000;\n\t"                             \
        "mov.b64 s, {lo, hi};\n\t"                                    \
        "fma.rn.f32x2 %0, s, %3, %0;\n\t"                             \
        "}" : "+l"(ACC) : "l"(QP), "l"(KP), "l"(WP))

__global__ void __launch_bounds__(512, 1)
mono_kernel(const float* __restrict__ emb,
            const float* __restrict__ prev,
            const float* __restrict__ Wq,
            const float* __restrict__ bq,
            const float* __restrict__ Wk,
            const float* __restrict__ bk,
            const float* __restrict__ Wc,
            const float* __restrict__ bc,
            const float* __restrict__ W1,
            const float* __restrict__ b1,
            const float* __restrict__ W2,
            const float* __restrict__ b2,
            float* __restrict__ out) {
    extern __shared__ float sm[];
    int t = threadIdx.x;
    int blk = blockIdx.x;
    int g = t >> 7, t128 = t & 127;          // 128-thread tile-group
    float* gbase = sm + g * GSTRIDE;

    // ===== PHASE 1: wfuse GEMM (blocks 0-15) + ctxbias (blocks 128-135) ====
    if (blk < 16) {
        // Wf = [Wq@W1top | Wk@W1bot]; 64 tiles (8n x 4e x 2k), one per group
        float* AsT = gbase;            // [64k][65e]
        float* Bs  = gbase + 64 * 65;  // [64k][32n]
        int wg = blk * 4 + g;
        int nb = (wg & 7) * 32;
        int e0 = ((wg >> 3) & 3) * 64;
        int k0 = ((wg >> 5) & 1) * 64;
        int half = nb >> 7;
        int ncol = nb & 127;
        const float* A = half ? Wk : Wq;
        int tx = t128 & 7, ty = t128 >> 3;

        #pragma unroll
        for (int l = 0; l < 8; l++) {          // A: 64(e) x 64(k), transposed
            int idx = l * 128 + t128;
            int e16 = idx & 15, i = idx >> 4;
            float4 v = *(const float4*)&A[(e0 + i) * HD + k0 + 4 * e16];
            AsT[(4 * e16 + 0) * 65 + i] = v.x;
            AsT[(4 * e16 + 1) * 65 + i] = v.y;
            AsT[(4 * e16 + 2) * 65 + i] = v.z;
            AsT[(4 * e16 + 3) * 65 + i] = v.w;
        }
        #pragma unroll
        for (int l = 0; l < 4; l++) {          // B: 64x32
            int idx = l * 128 + t128;
            int c4 = idx & 7, row = idx >> 3;
            *(float4*)&Bs[row * 32 + 4 * c4] =
                *(const float4*)&W1[(half * HD + k0 + row) * HD + ncol + 4 * c4];
        }
        __syncthreads();
        float acc[4][4] = {};
        #pragma unroll 4
        for (int k = 0; k < 64; k++) {
            float a0 = AsT[k * 65 + 4 * ty + 0];
            float a1 = AsT[k * 65 + 4 * ty + 1];
            float a2 = AsT[k * 65 + 4 * ty + 2];
            float a3 = AsT[k * 65 + 4 * ty + 3];
            float4 b = *(const float4*)&Bs[k * 32 + 4 * tx];
            acc[0][0] = fmaf(a0, b.x, acc[0][0]); acc[0][1] = fmaf(a0, b.y, acc[0][1]);
            acc[0][2] = fmaf(a0, b.z, acc[0][2]); acc[0][3] = fmaf(a0, b.w, acc[0][3]);
            acc[1][0] = fmaf(a1, b.x, acc[1][0]); acc[1][1] = fmaf(a1, b.y, acc[1][1]);
            acc[1][2] = fmaf(a1, b.z, acc[1][2]); acc[1][3] = fmaf(a1, b.w, acc[1][3]);
            acc[2][0] = fmaf(a2, b.x, acc[2][0]); acc[2][1] = fmaf(a2, b.y, acc[2][1]);
            acc[2][2] = fmaf(a2, b.z, acc[2][2]); acc[2][3] = fmaf(a2, b.w, acc[2][3]);
            acc[3][0] = fmaf(a3, b.x, acc[3][0]); acc[3][1] = fmaf(a3, b.y, acc[3][1]);
            acc[3][2] = fmaf(a3, b.z, acc[3][2]); acc[3][3] = fmaf(a3, b.w, acc[3][3]);
        }
        float* outp = ((wg >> 5) & 1) ? g_WfB : g_WfA;
        #pragma unroll
        for (int r = 0; r < 4; r++)
            *(float4*)&outp[(e0 + 4 * ty + r) * 256 + nb + 4 * tx] =
                make_float4(acc[r][0], acc[r][1], acc[r][2], acc[r][3]);
    } else if (blk >= 128) {
        // blocks 128-135: redundant ctx, then 32 bias-GEMV columns each.
        float* semb  = sm;                    // 256
        float* part1 = sm + 256;              // [4][128]
        float* sqk   = sm + 256 + 512;        // [2][128]
        float* part2 = sm + 256 + 512 + 256;  // [16][32]
        int cb = (blk - 128) * 32;            // column base 0..224
        if (t < 256) semb[t] = emb[t];
        __syncthreads();
        {   // ctx matvec: 4 partials per h, 64-deep as 8 chains of 8
            int p = t >> 7, h = t & 127;
            int kb = p * 64;
            float s[8] = {};
            #pragma unroll
            for (int c = 0; c < 8; c++)
                #pragma unroll
                for (int k = 0; k < 8; k++) {
                    int idx = kb + c * 8 + k;
                    s[c] = fmaf(semb[idx], Wc[idx * HD + h], s[c]);
                }
            part1[p * 128 + h] = ((s[0]+s[1])+(s[2]+s[3]))+((s[4]+s[5])+(s[6]+s[7]));
        }
        __syncthreads();
        if (t < 128) {
            float v = bc[t] + part1[t] + part1[128 + t] + part1[256 + t] + part1[384 + t];
            float ctx = fmaxf(v, 0.f);
            sqk[t] = bq[t] + ctx;
            sqk[128 + t] = bk[t] + ctx;
        }
        __syncthreads();
        {   // bias GEMV for 32 columns: 16 partials per col, 8-deep each
            int col = cb + (t & 31);          // 0..255
            int p = t >> 5;                   // 0..15
            int half = col >> 7, colh = col & 127;
            float s = 0.f;
            #pragma unroll
            for (int k = 0; k < 8; k++) {
                int kk = p * 8 + k;
                s = fmaf(sqk[half * 128 + kk],
                         W1[(half * HD + kk) * HD + colh], s);
            }
            part2[p * 32 + (t & 31)] = s;
        }
        __syncthreads();
        if (t < 32) {
            int col = cb + t;
            float s = (col < HD) ? b1[col] : 0.f;
            #pragma unroll
            for (int p = 0; p < 16; p++) s += part2[p * 32 + t];
            g_biasf[col] = s;
        }
    }

    grid_barrier(&g_bar1);

    // ================= PHASE 2: qk GEMM, 512 tiles (8n x 16m x 4k) =========
    if (blk < 128) {
        float* AsT = gbase;            // [64k][65m]
        float* Bs  = gbase + 64 * 65;  // [64k][32n]
        int wg = blk * 4 + g;          // 0..511
        int nb = (wg & 7) * 32;
        int i0 = ((wg >> 3) & 15) * 64;
        int z  = wg >> 7;
        int k0 = z * 64;
        int tx = t128 & 7, ty = t128 >> 3;

        #pragma unroll
        for (int l = 0; l < 8; l++) {          // A: 64(m) x 64(k), transposed
            int idx = l * 128 + t128;
            int e16 = idx & 15, i = idx >> 4;
            float4 v = *(const float4*)&prev[(i0 + i) * ED + k0 + 4 * e16];
            AsT[(4 * e16 + 0) * 65 + i] = v.x;
            AsT[(4 * e16 + 1) * 65 + i] = v.y;
            AsT[(4 * e16 + 2) * 65 + i] = v.z;
            AsT[(4 * e16 + 3) * 65 + i] = v.w;
        }
        #pragma unroll
        for (int l = 0; l < 4; l++) {          // B: 64x32, sum wfuse partials
            int idx = l * 128 + t128;
            int c4 = idx & 7, row = idx >> 3;
            int off = (k0 + row) * 256 + nb + 4 * c4;
            float4 a = *(const float4*)&g_WfA[off];
            float4 b = *(const float4*)&g_WfB[off];
            *(float4*)&Bs[row * 32 + 4 * c4] =
                make_float4(a.x + b.x, a.y + b.y, a.z + b.z, a.w + b.w);
        }
        __syncthreads();
        float acc[4][4] = {};
        #pragma unroll 4
        for (int k = 0; k < 64; k++) {
            float a0 = AsT[k * 65 + 4 * ty + 0];
            float a1 = AsT[k * 65 + 4 * ty + 1];
            float a2 = AsT[k * 65 + 4 * ty + 2];
            float a3 = AsT[k * 65 + 4 * ty + 3];
            float4 b = *(const float4*)&Bs[k * 32 + 4 * tx];
            acc[0][0] = fmaf(a0, b.x, acc[0][0]); acc[0][1] = fmaf(a0, b.y, acc[0][1]);
            acc[0][2] = fmaf(a0, b.z, acc[0][2]); acc[0][3] = fmaf(a0, b.w, acc[0][3]);
            acc[1][0] = fmaf(a1, b.x, acc[1][0]); acc[1][1] = fmaf(a1, b.y, acc[1][1]);
            acc[1][2] = fmaf(a1, b.z, acc[1][2]); acc[1][3] = fmaf(a1, b.w, acc[1][3]);
            acc[2][0] = fmaf(a2, b.x, acc[2][0]); acc[2][1] = fmaf(a2, b.y, acc[2][1]);
            acc[2][2] = fmaf(a2, b.z, acc[2][2]); acc[2][3] = fmaf(a2, b.w, acc[2][3]);
            acc[3][0] = fmaf(a3, b.x, acc[3][0]); acc[3][1] = fmaf(a3, b.y, acc[3][1]);
            acc[3][2] = fmaf(a3, b.z, acc[3][2]); acc[3][3] = fmaf(a3, b.w, acc[3][3]);
        }
        float* outp = g_qk4 + z * QK;
        #pragma unroll
        for (int r = 0; r < 4; r++)
            *(float4*)&outp[(i0 + 4 * ty + r) * 256 + nb + 4 * tx] =
                make_float4(acc[r][0], acc[r][1], acc[r][2], acc[r][3]);
    }

    grid_barrier(&g_bar2);

    // ================= PHASE 3: pair scores (R6 body, unroll 4) ============
    {
        float* qs  = sm;                      // [64][128] swizzled
        float* ks  = sm + TSP * HD;           // [64][128] swizzled
        float* w2s = sm + 2 * TSP * HD;       // [128]
        float* red = sm + 2 * TSP * HD + HD;  // [64][65] scratch

        int rem = blk;
        int it = 0;
        #pragma unroll
        for (int r = 0; r < 16; r++) {
            int len = 16 - r;
            if (rem < len) { it = r; break; }
            rem -= len;
        }
        int jt = it + rem;
        int ibase = it * TSP, jbase = jt * TSP;

        {   // loader: sum 4 split-K partials + fold fused bias, swizzle rows
            int h4 = t & 31;
            float4 bq4 = *(const float4*)&g_biasf[4 * h4];
            float4 bk4 = *(const float4*)&g_biasf[HD + 4 * h4];
            #pragma unroll
            for (int l = 0; l < 4; l++) {
                int i = (t >> 5) + 16 * l;
                int qo = (ibase + i) * 256 + 4 * h4;
                int ko = (jbase + i) * 256 + HD + 4 * h4;
                float4 qv = bq4, kv = bk4;
                #pragma unroll
                for (int z = 0; z < 4; z++) {
                    float4 qa = *(const float4*)&g_qk4[z * QK + qo];
                    float4 ka = *(const float4*)&g_qk4[z * QK + ko];
                    qv.x += qa.x; qv.y += qa.y; qv.z += qa.z; qv.w += qa.w;
                    kv.x += ka.x; kv.y += ka.y; kv.z += ka.z; kv.w += ka.w;
                }
                int sw = 4 * (h4 ^ ((i >> 2) & 7));
                *(float4*)&qs[i * HD + sw] = qv;
                *(float4*)&ks[i * HD + sw] = kv;
            }
        }
        if (t < HD) w2s[t] = W2[t];
        __syncthreads();

        int hg = t >> 8;
        int tt = t & 255;
        int tx = tt & 15, ty = tt >> 4;
        int i0 = ty * 4, j0 = tx * 4;
        int swq = ty & 7, swk = tx & 7;

        unsigned long long acc[4][4];
        #pragma unroll
        for (int a = 0; a < 4; a++)
            #pragma unroll
            for (int b = 0; b < 4; b++)
                acc[a][b] = 0ull;

        int h4beg = hg * 16;
        #pragma unroll 4
        for (int hh = 0; hh < 16; hh++) {
            int h4 = h4beg + hh;
            int hq = 4 * (h4 ^ swq);
            int hk = 4 * (h4 ^ swk);
            ulonglong2 q[4], k[4];
            #pragma unroll
            for (int a = 0; a < 4; a++)
                q[a] = *(const ulonglong2*)&qs[(i0 + a) * HD + hq];
            #pragma unroll
            for (int b = 0; b < 4; b++)
                k[b] = *(const ulonglong2*)&ks[(j0 + b) * HD + hk];
            ulonglong2 w = *(const ulonglong2*)&w2s[4 * h4];
            #pragma unroll
            for (int a = 0; a < 4; a++)
                #pragma unroll
                for (int b = 0; b < 4; b++) {
                    PSTEP(acc[a][b], q[a].x, k[b].x, w.x);
                    PSTEP(acc[a][b], q[a].y, k[b].y, w.y);
                }
        }

        float s[4][4];
        #pragma unroll
        for (int a = 0; a < 4; a++)
            #pragma unroll
            for (int b = 0; b < 4; b++) {
                unsigned long long v = acc[a][b];
                s[a][b] = __int_as_float((unsigned)v) +
                          __int_as_float((unsigned)(v >> 32));
            }

        if (hg) {
            #pragma unroll
            for (int a = 0; a < 4; a++)
                #pragma unroll
                for (int b = 0; b < 4; b++)
                    red[(i0 + a) * 65 + j0 + b] = s[a][b];
        }
        __syncthreads();

        if (!hg) {
            float bias = b2[0];
            #pragma unroll
            for (int a = 0; a < 4; a++) {
                int i = ibase + i0 + a;
                int rowoff = i * N - ((i * (i + 1)) >> 1) - i - 1;
                #pragma unroll
                for (int b = 0; b < 4; b++) {
                    int j = jbase + j0 + b;
                    if (i < j)
                        out[rowoff + j] =
                            s[a][b] + red[(i0 + a) * 65 + j0 + b] + bias;
                }
            }
        }
    }
}

// ---------------- launch ----------------
extern "C" void kernel_launch(void* const* d_in, const int* in_sizes, int n_in,
                              void* d_out, int out_size) {
    const float* emb  = (const float*)d_in[0];
    const float* prev = (const float*)d_in[1];
    const float* Wq   = (const float*)d_in[2];
    const float* bq   = (const float*)d_in[3];
    const float* Wk   = (const float*)d_in[4];
    const float* bk   = (const float*)d_in[5];
    const float* Wc   = (const float*)d_in[6];
    const float* bc   = (const float*)d_in[7];
    const float* W1   = (const float*)d_in[8];
    const float* b1   = (const float*)d_in[9];
    const float* W2   = (const float*)d_in[10];
    const float* b2   = (const float*)d_in[11];
    float* out = (float*)d_out;

    // smem = max(phase1/2: 4 groups * GSTRIDE, phase3: 20672 floats)
    int smem = 4 * GSTRIDE * (int)sizeof(float);                     // 99328
    cudaFuncSetAttribute(mono_kernel,
                         cudaFuncAttributeMaxDynamicSharedMemorySize, smem);

    mono_kernel<<<NB, 512, smem>>>(emb, prev, Wq, bq, Wk, bk, Wc, bc,
                                   W1, b1, W2, b2, out);
}